// round 6
// baseline (speedup 1.0000x reference)
#include <cuda_runtime.h>
#include <math.h>

// YOLOv1 loss — chunked streaming kernel A (unchanged; measured ~16.8us,
// ~5.7TB/s) + pairing kernel B with smem staging AND early-exit existence
// loop (R5's branchless inner loop ran all ~20 iterations; random boxes
// overlap with high probability so expected first-hit is ~1-2 iterations).
//
// Exactness: max_iou is only compared against 0 and union>0 always
// (w,h >= 0.05), so cmask == "exists masked pred box with intersection > 0".
// Intersection arithmetic (cx - 0.5f*w, min/max/sub, >0) matches the
// reference ops exactly; box floats pass through scratch unmodified.
//
// Graph-replay invariants: g_acc / g_boxcnt / g_count are zero at every
// launch; kernel B's last CTA restores all of them.

#define CELLS 49
#define CH 30
#define FPS (CELLS * CH)        // 1470 floats per sample
#define CHUNK 64                // cells per CTA in kernel A
#define CHUNK_F (CHUNK * CH)    // 1920 floats
#define MAXB 8192
#define NSLOT 128
#define RECF 980                // 49 cells * 20 floats per sample record block
#define WARPS_B 8
#define NCTA_B_MAX ((MAXB + WARPS_B - 1) / WARPS_B)

__device__ float  g_boxes[MAXB * RECF];             // compacted obj-box records
__device__ int    g_boxcnt[MAXB];                   // boxes per sample (zeroed by B)
__device__ double g_acc[2 * NSLOT];                 // [0]=noobj [1]=cls (zeroed by B)
__device__ float  g_partB[NCTA_B_MAX * 2];          // per-CTA coord/objc partials
__device__ unsigned int g_count = 0;

// ---------------------------------------------------------------------------
// Kernel A: one CTA per 64-cell chunk. float4 staging -> per-cell compute.
// ---------------------------------------------------------------------------
__global__ __launch_bounds__(256) void yolo_chunk_kernel(
    const float* __restrict__ pred, const float* __restrict__ target,
    int ncells, int total_floats)
{
    __shared__ float sp[CHUNK_F];
    __shared__ float st[CHUNK_F];
    __shared__ float sN[8], sC[8];

    const int tid  = threadIdx.x;
    const int c0   = blockIdx.x * CHUNK;
    const int f0   = c0 * CH;                         // 1920*blk -> 16B aligned
    const int flen = min(CHUNK_F, total_floats - f0);

    {
        const int nv4 = flen >> 2;
        const float4* gp4 = (const float4*)(pred + f0);
        const float4* gt4 = (const float4*)(target + f0);
        float4* sp4 = (float4*)sp;
        float4* st4 = (float4*)st;
        #pragma unroll 2
        for (int i = tid; i < nv4; i += 256) {
            sp4[i] = gp4[i];
            st4[i] = gt4[i];
        }
        for (int i = (nv4 << 2) + tid; i < flen; i += 256) {
            sp[i] = pred[f0 + i];
            st[i] = target[f0 + i];
        }
    }
    __syncthreads();

    float accN = 0.f, accC = 0.f;
    if (tid < CHUNK && c0 + tid < ncells) {
        const int cell = c0 + tid;
        const float* pc = sp + tid * CH;
        const float* tc = st + tid * CH;
        if (tc[4] == 0.f) {
            const float d4 = pc[4] - tc[4];
            const float d9 = pc[9] - tc[9];
            accN = d4 * d4 + d9 * d9;
        } else {
            float s = 0.f;
            #pragma unroll
            for (int k = 10; k < CH; k++) {
                const float d = pc[k] - tc[k];
                s += d * d;
            }
            accC = s;
            const int b = cell / CELLS;
            const int slot = atomicAdd(&g_boxcnt[b], 1);
            float* rec = g_boxes + (size_t)b * RECF + slot * 20;
            #pragma unroll
            for (int k = 0; k < 10; k++) {
                rec[k]      = pc[k];
                rec[10 + k] = tc[k];
            }
        }
    }

    #pragma unroll
    for (int o = 16; o > 0; o >>= 1) {
        accN += __shfl_down_sync(0xffffffffu, accN, o);
        accC += __shfl_down_sync(0xffffffffu, accC, o);
    }
    const int lane = tid & 31, warp = tid >> 5;
    if (lane == 0) { sN[warp] = accN; sC[warp] = accC; }
    __syncthreads();
    if (tid == 0) {
        float n = 0.f, c = 0.f;
        #pragma unroll
        for (int w = 0; w < 8; w++) { n += sN[w]; c += sC[w]; }
        const int slot = blockIdx.x & (NSLOT - 1);
        atomicAdd(&g_acc[0 * NSLOT + slot], (double)n);
        atomicAdd(&g_acc[1 * NSLOT + slot], (double)c);
    }
}

// ---------------------------------------------------------------------------
// Kernel B: warp-per-sample pairing (smem staging + early-exit) + last-CTA final.
// ---------------------------------------------------------------------------
__global__ __launch_bounds__(32 * WARPS_B) void yolo_pair_final_kernel(
    float* __restrict__ out, int B, int nctaB)
{
    __shared__ float sbox[WARPS_B][RECF];
    __shared__ float sCo[WARPS_B], sOb[WARPS_B];
    __shared__ int s_last;

    const int tid  = threadIdx.x;
    const int lane = tid & 31;
    const int warp = tid >> 5;
    const int b    = blockIdx.x * WARPS_B + warp;

    float coord = 0.f, objc = 0.f;

    if (b < B) {
        const int cnt  = g_boxcnt[b];
        const int nbox = 2 * cnt;

        // coalesced float4 staging of this sample's records
        const int nf4 = cnt * 5;                      // cnt*20 floats / 4
        const float4* src = (const float4*)(g_boxes + (size_t)b * RECF);
        float4* dst = (float4*)sbox[warp];
        for (int i = lane; i < nf4; i += 32)
            dst[i] = src[i];
        __syncwarp();

        const float* base = sbox[warp];
        for (int i = lane; i < nbox; i += 32) {
            const int roff = (i >> 1) * 20 + 5 * (i & 1);
            const float tcx = base[roff + 10], tcy = base[roff + 11];
            const float tw  = base[roff + 12], th  = base[roff + 13];
            const float tx0 = tcx - 0.5f * tw, ty0 = tcy - 0.5f * th;
            const float tx1 = tcx + 0.5f * tw, ty1 = tcy + 0.5f * th;

            bool found = false;
            for (int j = 0; j < nbox; j++) {
                const int po = (j >> 1) * 20 + 5 * (j & 1);
                const float pcx = base[po],     pcy = base[po + 1];
                const float pw  = base[po + 2], ph  = base[po + 3];
                const float ix = fminf(pcx + 0.5f * pw, tx1) - fmaxf(pcx - 0.5f * pw, tx0);
                const float iy = fminf(pcy + 0.5f * ph, ty1) - fmaxf(pcy - 0.5f * ph, ty0);
                if (ix > 0.f && iy > 0.f && ix * iy > 0.f) { found = true; break; }
            }
            if (found) {
                const float dx = base[roff + 0] - tcx;
                const float dy = base[roff + 1] - tcy;
                const float dw = sqrtf(base[roff + 2]) - sqrtf(tw);
                const float dh = sqrtf(base[roff + 3]) - sqrtf(th);
                coord += dx * dx + dy * dy + dw * dw + dh * dh;
                const float dc = base[roff + 4] - base[roff + 14];
                objc += dc * dc;
            }
        }
    }

    #pragma unroll
    for (int o = 16; o > 0; o >>= 1) {
        coord += __shfl_down_sync(0xffffffffu, coord, o);
        objc  += __shfl_down_sync(0xffffffffu, objc, o);
    }
    if (lane == 0) {
        sCo[warp] = coord;
        sOb[warp] = objc;
        if (b < B) g_boxcnt[b] = 0;                   // restore replay invariant
    }
    __syncthreads();

    if (tid == 0) {
        float pc = 0.f, po = 0.f;
        #pragma unroll
        for (int w = 0; w < WARPS_B; w++) { pc += sCo[w]; po += sOb[w]; }
        g_partB[blockIdx.x * 2 + 0] = pc;
        g_partB[blockIdx.x * 2 + 1] = po;
        __threadfence();
        const unsigned int old = atomicAdd(&g_count, 1u);
        s_last = (old == (unsigned int)(nctaB - 1)) ? 1 : 0;
    }
    __syncthreads();

    if (!s_last) return;

    // final reduction (one CTA)
    double a0 = 0.0, a1 = 0.0, a2 = 0.0, a3 = 0.0;
    for (int i = tid; i < NSLOT; i += 32 * WARPS_B) {
        a0 += g_acc[0 * NSLOT + i];
        a1 += g_acc[1 * NSLOT + i];
        g_acc[0 * NSLOT + i] = 0.0;
        g_acc[1 * NSLOT + i] = 0.0;
    }
    for (int i = tid; i < nctaB; i += 32 * WARPS_B) {
        a2 += (double)g_partB[i * 2 + 0];
        a3 += (double)g_partB[i * 2 + 1];
    }
    #pragma unroll
    for (int o = 16; o > 0; o >>= 1) {
        a0 += __shfl_down_sync(0xffffffffu, a0, o);
        a1 += __shfl_down_sync(0xffffffffu, a1, o);
        a2 += __shfl_down_sync(0xffffffffu, a2, o);
        a3 += __shfl_down_sync(0xffffffffu, a3, o);
    }
    __shared__ double sd[4][WARPS_B];
    if (lane == 0) { sd[0][warp] = a0; sd[1][warp] = a1; sd[2][warp] = a2; sd[3][warp] = a3; }
    __syncthreads();
    if (tid == 0) {
        double r0 = 0, r1 = 0, r2 = 0, r3 = 0;
        #pragma unroll
        for (int w = 0; w < WARPS_B; w++) {
            r0 += sd[0][w]; r1 += sd[1][w]; r2 += sd[2][w]; r3 += sd[3][w];
        }
        const double inv = 1.0 / (double)B;
        const double cls_l = r1 * inv;
        const double obj_l = (r3 + 0.5 * r0) * inv;
        const double crd_l = r2 * 5.0 * inv;
        out[0] = (float)(cls_l + obj_l + crd_l);
        out[1] = (float)cls_l;
        out[2] = (float)obj_l;
        out[3] = (float)crd_l;
        g_count = 0u;
    }
}

extern "C" void kernel_launch(void* const* d_in, const int* in_sizes, int n_in,
                              void* d_out, int out_size)
{
    const float* pred = (const float*)d_in[0];
    const float* target = (const float*)d_in[1];
    const int B = in_sizes[0] / FPS;
    const int ncells = B * CELLS;
    const int total_floats = B * FPS;
    const int nctaA = (ncells + CHUNK - 1) / CHUNK;
    const int nctaB = (B + WARPS_B - 1) / WARPS_B;

    yolo_chunk_kernel<<<nctaA, 256>>>(pred, target, ncells, total_floats);
    yolo_pair_final_kernel<<<nctaB, 32 * WARPS_B>>>((float*)d_out, B, nctaB);
}